// round 3
// baseline (speedup 1.0000x reference)
#include <cuda_runtime.h>

// KREmbedding: Gaussian-weighted context embedding aggregation.
// context: [B, C] int32, center: [B] int32, W: [V, D] float32 -> out [B, D] float32
// B=8192, C=32, D=512, SIGMA=1.0
//
// Round 3: one warp per b; center row parked in lane-private SMEM to free 16
// registers so the unroll-2 software pipeline can keep TWO full row buffers in
// flight and interleave consecutive iterations' shfl-reduce chains.
// Output stored with streaming hint (__stcs) to keep W resident in L2.

#define KB_B 8192
#define KB_C 32
#define KB_D 512
#define NTHREADS 256
#define WARPS_PER_BLOCK (NTHREADS / 32)

__global__ __launch_bounds__(NTHREADS)
void kre_kernel(const int* __restrict__ context,
                const int* __restrict__ center,
                const float* __restrict__ W,
                float* __restrict__ out)
{
    const int lane = threadIdx.x & 31;
    const int wid  = threadIdx.x >> 5;
    const int b    = blockIdx.x * WARPS_PER_BLOCK + wid;
    if (b >= KB_B) return;

    // lane-private center stash: each lane only ever reads back its own writes,
    // so no synchronization is needed. float4-indexed lane+32i -> LDS.128,
    // 8 consecutive lanes cover one 128B phase -> conflict-free.
    __shared__ float4 s_cen[WARPS_PER_BLOCK][KB_D / 4];

    const int my_idx  = __ldg(&context[b * KB_C + lane]);
    const int cen_idx = __ldg(&center[b]);

    const float4* cenp = reinterpret_cast<const float4*>(W + (size_t)cen_idx * KB_D);
#pragma unroll
    for (int i = 0; i < 4; i++) s_cen[wid][lane + 32 * i] = __ldg(&cenp[lane + 32 * i]);

    float4 acc[4];
#pragma unroll
    for (int i = 0; i < 4; i++) acc[i] = make_float4(0.f, 0.f, 0.f, 0.f);
    float esum = 0.f;

#pragma unroll 2
    for (int c = 0; c < KB_C; c++) {
        const int idx = __shfl_sync(0xffffffffu, my_idx, c);
        const float4* rowp = reinterpret_cast<const float4*>(W + (size_t)idx * KB_D);
        float4 r[4];
#pragma unroll
        for (int i = 0; i < 4; i++) r[i] = __ldg(&rowp[lane + 32 * i]);

        float d2 = 0.f;
#pragma unroll
        for (int i = 0; i < 4; i++) {
            const float4 cv = s_cen[wid][lane + 32 * i];
            float dx = r[i].x - cv.x; d2 = fmaf(dx, dx, d2);
            float dy = r[i].y - cv.y; d2 = fmaf(dy, dy, d2);
            float dz = r[i].z - cv.z; d2 = fmaf(dz, dz, d2);
            float dw = r[i].w - cv.w; d2 = fmaf(dw, dw, d2);
        }
#pragma unroll
        for (int off = 16; off; off >>= 1)
            d2 += __shfl_xor_sync(0xffffffffu, d2, off);

        const float e = __expf(-0.5f * d2);   // fp32 underflow-to-0 matches reference
        esum += e;
#pragma unroll
        for (int i = 0; i < 4; i++) {
            acc[i].x = fmaf(e, r[i].x, acc[i].x);
            acc[i].y = fmaf(e, r[i].y, acc[i].y);
            acc[i].z = fmaf(e, r[i].z, acc[i].z);
            acc[i].w = fmaf(e, r[i].w, acc[i].w);
        }
    }

    const float inv = 1.0f / (esum + 1e-8f);
    float4* op = reinterpret_cast<float4*>(out + (size_t)b * KB_D);
#pragma unroll
    for (int i = 0; i < 4; i++) {
        float4 v = acc[i];
        v.x *= inv; v.y *= inv; v.z *= inv; v.w *= inv;
        __stcs(&op[lane + 32 * i], v);   // streaming store: don't pollute L2
    }
}

extern "C" void kernel_launch(void* const* d_in, const int* in_sizes, int n_in,
                              void* d_out, int out_size)
{
    const int* context = (const int*)d_in[0];
    const int* center  = (const int*)d_in[1];
    const float* W     = (const float*)d_in[2];
    for (int i = 0; i < n_in; i++) {
        if (in_sizes[i] == KB_B * KB_C)      context = (const int*)d_in[i];
        else if (in_sizes[i] == KB_B)        center  = (const int*)d_in[i];
        else if (in_sizes[i] > KB_B * KB_C)  W       = (const float*)d_in[i];
    }
    float* out = (float*)d_out;
    const int nblocks = (KB_B + WARPS_PER_BLOCK - 1) / WARPS_PER_BLOCK;
    kre_kernel<<<nblocks, NTHREADS>>>(context, center, W, out);
}

// round 4
// speedup vs baseline: 1.6471x; 1.6471x over previous
#include <cuda_runtime.h>

// KREmbedding: Gaussian-weighted context embedding aggregation.
// context: [B, C] int32, center: [B] int32, W: [V, D] float32 -> out [B, D] float32
// B=8192, C=32, D=512, SIGMA=1.0
//
// Round 4: early-exit lower-bound cascade.
//   w = expf(-d2/2) underflows to EXACTLY 0.0f when d2 > 207 (2^-149 cutoff).
//   Partial sums of squares are lower bounds on d2, so if the partial distance
//   over the first 128 (then 256) elements exceeds 220 (conservative margin),
//   the row provably contributes exactly 0 to both esum and acc — in the fp32
//   reference as well (exp(-110)=1.7e-48 < min subnormal). Skip the rest.
//   The branch is warp-uniform (butterfly reduction is bitwise-identical across
//   lanes: each level both lanes compute a+b / b+a, commutative in IEEE).
//   Rows that survive the cascade get the FULL exact 512-element computation.
//
//   acc lives in warp-private SMEM (touched only on the rare surviving path),
//   cen keeps only its first half in registers -> ~40 regs -> high occupancy.

#define KB_B 8192
#define KB_C 32
#define KB_D 512
#define NTHREADS 128
#define WARPS_PER_BLOCK (NTHREADS / 32)
#define T_SKIP 220.0f

__device__ __forceinline__ float warp_sum(float v) {
#pragma unroll
    for (int off = 16; off; off >>= 1)
        v += __shfl_xor_sync(0xffffffffu, v, off);
    return v;
}

__device__ __forceinline__ float quarter_d2(float4 r, float4 c) {
    float dx = r.x - c.x, dy = r.y - c.y, dz = r.z - c.z, dw = r.w - c.w;
    float d = dx * dx;
    d = fmaf(dy, dy, d);
    d = fmaf(dz, dz, d);
    d = fmaf(dw, dw, d);
    return d;
}

__global__ __launch_bounds__(NTHREADS)
void kre_kernel(const int* __restrict__ context,
                const int* __restrict__ center,
                const float* __restrict__ W,
                float* __restrict__ out)
{
    const int lane = threadIdx.x & 31;
    const int wid  = threadIdx.x >> 5;
    const int b    = blockIdx.x * WARPS_PER_BLOCK + wid;

    // warp-private accumulator slice; only this warp's lanes touch it -> no sync
    __shared__ float4 s_acc[WARPS_PER_BLOCK][KB_D / 4];
#pragma unroll
    for (int i = 0; i < 4; i++)
        s_acc[wid][lane + 32 * i] = make_float4(0.f, 0.f, 0.f, 0.f);

    const int my_idx  = __ldg(&context[b * KB_C + lane]);
    const int cen_idx = __ldg(&center[b]);
    const float4* cenp = reinterpret_cast<const float4*>(W + (size_t)cen_idx * KB_D);
    const float4 cen0 = __ldg(&cenp[lane]);
    const float4 cen1 = __ldg(&cenp[lane + 32]);

    float esum = 0.f;

    for (int c = 0; c < KB_C; c++) {
        const int idx = __shfl_sync(0xffffffffu, my_idx, c);
        const float4* rowp = reinterpret_cast<const float4*>(W + (size_t)idx * KB_D);

        // stage 1: first 128 elements (1 float4 per lane)
        const float4 r0 = __ldg(&rowp[lane]);
        float t = warp_sum(quarter_d2(r0, cen0));
        if (t > T_SKIP) continue;                 // provably w == 0.0f

        // stage 2: next 128 elements
        const float4 r1 = __ldg(&rowp[lane + 32]);
        t += warp_sum(quarter_d2(r1, cen1));
        if (t > T_SKIP) continue;                 // provably w == 0.0f

        // rare exact path: finish the full 512-element distance
        {
            const float4 cen2 = __ldg(&cenp[lane + 64]);
            const float4 cen3 = __ldg(&cenp[lane + 96]);
            const float4 r2 = __ldg(&rowp[lane + 64]);
            const float4 r3 = __ldg(&rowp[lane + 96]);
            const float d2 = t + warp_sum(quarter_d2(r2, cen2) + quarter_d2(r3, cen3));

            const float e = __expf(-0.5f * d2);
            esum += e;

            float4 a;
            a = s_acc[wid][lane];
            a.x = fmaf(e, r0.x, a.x); a.y = fmaf(e, r0.y, a.y);
            a.z = fmaf(e, r0.z, a.z); a.w = fmaf(e, r0.w, a.w);
            s_acc[wid][lane] = a;
            a = s_acc[wid][lane + 32];
            a.x = fmaf(e, r1.x, a.x); a.y = fmaf(e, r1.y, a.y);
            a.z = fmaf(e, r1.z, a.z); a.w = fmaf(e, r1.w, a.w);
            s_acc[wid][lane + 32] = a;
            a = s_acc[wid][lane + 64];
            a.x = fmaf(e, r2.x, a.x); a.y = fmaf(e, r2.y, a.y);
            a.z = fmaf(e, r2.z, a.z); a.w = fmaf(e, r2.w, a.w);
            s_acc[wid][lane + 64] = a;
            a = s_acc[wid][lane + 96];
            a.x = fmaf(e, r3.x, a.x); a.y = fmaf(e, r3.y, a.y);
            a.z = fmaf(e, r3.z, a.z); a.w = fmaf(e, r3.w, a.w);
            s_acc[wid][lane + 96] = a;
        }
    }

    const float inv = 1.0f / (esum + 1e-8f);
    float4* op = reinterpret_cast<float4*>(out + (size_t)b * KB_D);
#pragma unroll
    for (int i = 0; i < 4; i++) {
        float4 v = s_acc[wid][lane + 32 * i];
        v.x *= inv; v.y *= inv; v.z *= inv; v.w *= inv;
        __stcs(&op[lane + 32 * i], v);
    }
}

extern "C" void kernel_launch(void* const* d_in, const int* in_sizes, int n_in,
                              void* d_out, int out_size)
{
    const int* context = (const int*)d_in[0];
    const int* center  = (const int*)d_in[1];
    const float* W     = (const float*)d_in[2];
    for (int i = 0; i < n_in; i++) {
        if (in_sizes[i] == KB_B * KB_C)      context = (const int*)d_in[i];
        else if (in_sizes[i] == KB_B)        center  = (const int*)d_in[i];
        else if (in_sizes[i] > KB_B * KB_C)  W       = (const float*)d_in[i];
    }
    float* out = (float*)d_out;
    const int nblocks = KB_B / WARPS_PER_BLOCK;
    kre_kernel<<<nblocks, NTHREADS>>>(context, center, W, out);
}

// round 5
// speedup vs baseline: 2.0012x; 1.2150x over previous
#include <cuda_runtime.h>

// KREmbedding: Gaussian-weighted context embedding aggregation.
// context: [B, C] int32, center: [B] int32, W: [V, D] float32 -> out [B, D] float32
// B=8192, C=32, D=512, SIGMA=1.0
//
// Round 5: 8-wide batched early-exit cascade.
//   expf(-d2/2) == 0.0f exactly when d2 > ~208 (fp32 underflow), and partial
//   sums of squares lower-bound d2, so rows whose first-128-element partial
//   exceeds 220 provably contribute nothing (identical in the fp32 reference).
//   Stage 1 runs 8 rows at once: 8 independent LDG.128 in flight (MLP=8),
//   8 interleaved butterfly trees (tree latency amortized 8x). Row data is
//   transient; the rare slow path reloads from L1 (const data -> identical).

#define KB_B 8192
#define KB_C 32
#define KB_D 512
#define NTHREADS 128
#define WARPS_PER_BLOCK (NTHREADS / 32)
#define BATCH 8
#define T_SKIP 220.0f

__device__ __forceinline__ float warp_sum(float v) {
#pragma unroll
    for (int off = 16; off; off >>= 1)
        v += __shfl_xor_sync(0xffffffffu, v, off);
    return v;
}

__device__ __forceinline__ float quarter_d2(float4 r, float4 c) {
    float dx = r.x - c.x, dy = r.y - c.y, dz = r.z - c.z, dw = r.w - c.w;
    float d = dx * dx;
    d = fmaf(dy, dy, d);
    d = fmaf(dz, dz, d);
    d = fmaf(dw, dw, d);
    return d;
}

// Cold path: row survived the 128-element bound (~6% of rows). Warp-uniform
// entry. Reloads row/center data from L1; exact full-distance computation,
// second bound after 256 elements, then exp + accumulate (collisions only).
__device__ __noinline__ void slow_path(const float4* __restrict__ rowp,
                                       const float4* __restrict__ cenp,
                                       float t1, int lane,
                                       float4* __restrict__ sacc,
                                       float& esum)
{
    const float4 r1   = __ldg(&rowp[lane + 32]);
    const float4 cen1 = __ldg(&cenp[lane + 32]);
    const float t2 = t1 + warp_sum(quarter_d2(r1, cen1));
    if (t2 > T_SKIP) return;                      // provably w == 0.0f

    const float4 r0   = __ldg(&rowp[lane]);       // L1-hot reload (const data)
    const float4 cen2 = __ldg(&cenp[lane + 64]);
    const float4 cen3 = __ldg(&cenp[lane + 96]);
    const float4 r2   = __ldg(&rowp[lane + 64]);
    const float4 r3   = __ldg(&rowp[lane + 96]);
    const float d2 = t2 + warp_sum(quarter_d2(r2, cen2) + quarter_d2(r3, cen3));

    const float e = __expf(-0.5f * d2);
    esum += e;

    float4 a;
    a = sacc[lane];
    a.x = fmaf(e, r0.x, a.x); a.y = fmaf(e, r0.y, a.y);
    a.z = fmaf(e, r0.z, a.z); a.w = fmaf(e, r0.w, a.w);
    sacc[lane] = a;
    a = sacc[lane + 32];
    a.x = fmaf(e, r1.x, a.x); a.y = fmaf(e, r1.y, a.y);
    a.z = fmaf(e, r1.z, a.z); a.w = fmaf(e, r1.w, a.w);
    sacc[lane + 32] = a;
    a = sacc[lane + 64];
    a.x = fmaf(e, r2.x, a.x); a.y = fmaf(e, r2.y, a.y);
    a.z = fmaf(e, r2.z, a.z); a.w = fmaf(e, r2.w, a.w);
    sacc[lane + 64] = a;
    a = sacc[lane + 96];
    a.x = fmaf(e, r3.x, a.x); a.y = fmaf(e, r3.y, a.y);
    a.z = fmaf(e, r3.z, a.z); a.w = fmaf(e, r3.w, a.w);
    sacc[lane + 96] = a;
}

__global__ __launch_bounds__(NTHREADS)
void kre_kernel(const int* __restrict__ context,
                const int* __restrict__ center,
                const float* __restrict__ W,
                float* __restrict__ out)
{
    const int lane = threadIdx.x & 31;
    const int wid  = threadIdx.x >> 5;
    const int b    = blockIdx.x * WARPS_PER_BLOCK + wid;

    // warp-private accumulator slice (rarely touched); no sync needed
    __shared__ float4 s_acc[WARPS_PER_BLOCK][KB_D / 4];
    float4* sacc = s_acc[wid];
#pragma unroll
    for (int i = 0; i < 4; i++)
        sacc[lane + 32 * i] = make_float4(0.f, 0.f, 0.f, 0.f);

    const int my_idx  = __ldg(&context[b * KB_C + lane]);
    const int cen_idx = __ldg(&center[b]);
    const float4* cenp = reinterpret_cast<const float4*>(W + (size_t)cen_idx * KB_D);
    const float4 cen0  = __ldg(&cenp[lane]);

    float esum = 0.f;

#pragma unroll
    for (int c0 = 0; c0 < KB_C; c0 += BATCH) {
        const float4* rp[BATCH];
        float p[BATCH];

        // 8 independent gathers in flight, then 8 short FMA chains
#pragma unroll
        for (int k = 0; k < BATCH; k++) {
            const int idx = __shfl_sync(0xffffffffu, my_idx, c0 + k);
            rp[k] = reinterpret_cast<const float4*>(W + (size_t)idx * KB_D);
        }
        float4 r[BATCH];
#pragma unroll
        for (int k = 0; k < BATCH; k++) r[k] = __ldg(&rp[k][lane]);
#pragma unroll
        for (int k = 0; k < BATCH; k++) p[k] = quarter_d2(r[k], cen0);

        // 8 interleaved butterfly trees: latency amortized 8x
#pragma unroll
        for (int off = 16; off; off >>= 1) {
#pragma unroll
            for (int k = 0; k < BATCH; k++)
                p[k] += __shfl_xor_sync(0xffffffffu, p[k], off);
        }

        // warp-uniform survivor dispatch (p identical across lanes)
#pragma unroll
        for (int k = 0; k < BATCH; k++) {
            if (p[k] <= T_SKIP)
                slow_path(rp[k], cenp, p[k], lane, sacc, esum);
        }
    }

    const float inv = 1.0f / (esum + 1e-8f);
    float4* op = reinterpret_cast<float4*>(out + (size_t)b * KB_D);
#pragma unroll
    for (int i = 0; i < 4; i++) {
        float4 v = sacc[lane + 32 * i];
        v.x *= inv; v.y *= inv; v.z *= inv; v.w *= inv;
        __stcs(&op[lane + 32 * i], v);
    }
}

extern "C" void kernel_launch(void* const* d_in, const int* in_sizes, int n_in,
                              void* d_out, int out_size)
{
    const int* context = (const int*)d_in[0];
    const int* center  = (const int*)d_in[1];
    const float* W     = (const float*)d_in[2];
    for (int i = 0; i < n_in; i++) {
        if (in_sizes[i] == KB_B * KB_C)      context = (const int*)d_in[i];
        else if (in_sizes[i] == KB_B)        center  = (const int*)d_in[i];
        else if (in_sizes[i] > KB_B * KB_C)  W       = (const float*)d_in[i];
    }
    float* out = (float*)d_out;
    const int nblocks = KB_B / WARPS_PER_BLOCK;
    kre_kernel<<<nblocks, NTHREADS>>>(context, center, W, out);
}

// round 6
// speedup vs baseline: 2.2247x; 1.1117x over previous
#include <cuda_runtime.h>

// KREmbedding: Gaussian-weighted context embedding aggregation.
// context: [B, C] int32, center: [B] int32, W: [V, D] float32 -> out [B, D] float32
// B=8192, C=32, D=512, SIGMA=1.0
//
// Round 6: batched early-exit cascade with INT REDUX bound test.
//   expf(-d2/2) == 0.0f exactly when d2 > ~208 (fp32 underflow). Partial sums
//   of squares lower-bound d2. Bound test per row: each lane converts its
//   128-element partial p to fixed point u = floor(min(p,60000)*1024) (<= 1024p,
//   exact shift), one redux.sync.add.s32 gives a warp-uniform S <= 1024*d2.
//   S > 220*1024 => d2 > 220 => weight is exactly 0 in the reference too.
//   Survivors (~13%) take a __noinline__ slow path with the exact fp32 tree.
//   Hot loop: 8 gathers in flight (MLP=8), zero shuffles trees, ~56 regs.

#define KB_B 8192
#define KB_C 32
#define KB_D 512
#define NTHREADS 128
#define WARPS_PER_BLOCK (NTHREADS / 32)
#define BATCH 8
#define T_SKIP 220.0f
#define T_INT (220 * 1024)

__device__ __forceinline__ float warp_sum(float v) {
#pragma unroll
    for (int off = 16; off; off >>= 1)
        v += __shfl_xor_sync(0xffffffffu, v, off);
    return v;
}

__device__ __forceinline__ float quarter_d2(float4 r, float4 c) {
    float dx = r.x - c.x, dy = r.y - c.y, dz = r.z - c.z, dw = r.w - c.w;
    float d = dx * dx;
    d = fmaf(dy, dy, d);
    d = fmaf(dz, dz, d);
    d = fmaf(dw, dw, d);
    return d;
}

// Cold path (warp-uniform entry, ~13% of rows; full exact path only for
// near/exact collisions). Recomputes everything from L1-hot data.
// Returns this row's weight e (0 if the 256-element bound kills it).
__device__ __noinline__ float slow_path(const float4* __restrict__ rowp,
                                        const float4* __restrict__ cenp,
                                        float4 cen0, int lane,
                                        float4* __restrict__ sacc)
{
    const float4 r0   = __ldg(&rowp[lane]);
    const float4 r1   = __ldg(&rowp[lane + 32]);
    const float4 cen1 = __ldg(&cenp[lane + 32]);
    const float t = warp_sum(quarter_d2(r0, cen0) + quarter_d2(r1, cen1));
    if (t > T_SKIP) return 0.f;                   // provably w == 0.0f (256-elem bound)

    const float4 cen2 = __ldg(&cenp[lane + 64]);
    const float4 cen3 = __ldg(&cenp[lane + 96]);
    const float4 r2   = __ldg(&rowp[lane + 64]);
    const float4 r3   = __ldg(&rowp[lane + 96]);
    const float d2 = t + warp_sum(quarter_d2(r2, cen2) + quarter_d2(r3, cen3));

    const float e = __expf(-0.5f * d2);

    float4 a;
    a = sacc[lane];
    a.x = fmaf(e, r0.x, a.x); a.y = fmaf(e, r0.y, a.y);
    a.z = fmaf(e, r0.z, a.z); a.w = fmaf(e, r0.w, a.w);
    sacc[lane] = a;
    a = sacc[lane + 32];
    a.x = fmaf(e, r1.x, a.x); a.y = fmaf(e, r1.y, a.y);
    a.z = fmaf(e, r1.z, a.z); a.w = fmaf(e, r1.w, a.w);
    sacc[lane + 32] = a;
    a = sacc[lane + 64];
    a.x = fmaf(e, r2.x, a.x); a.y = fmaf(e, r2.y, a.y);
    a.z = fmaf(e, r2.z, a.z); a.w = fmaf(e, r2.w, a.w);
    sacc[lane + 64] = a;
    a = sacc[lane + 96];
    a.x = fmaf(e, r3.x, a.x); a.y = fmaf(e, r3.y, a.y);
    a.z = fmaf(e, r3.z, a.z); a.w = fmaf(e, r3.w, a.w);
    sacc[lane + 96] = a;
    return e;
}

__global__ __launch_bounds__(NTHREADS)
void kre_kernel(const int* __restrict__ context,
                const int* __restrict__ center,
                const float* __restrict__ W,
                float* __restrict__ out)
{
    const int lane = threadIdx.x & 31;
    const int wid  = threadIdx.x >> 5;
    const int b    = blockIdx.x * WARPS_PER_BLOCK + wid;

    __shared__ float4 s_acc[WARPS_PER_BLOCK][KB_D / 4];   // warp-private, no sync
    float4* sacc = s_acc[wid];
#pragma unroll
    for (int i = 0; i < 4; i++)
        sacc[lane + 32 * i] = make_float4(0.f, 0.f, 0.f, 0.f);

    const int my_idx  = __ldg(&context[b * KB_C + lane]);
    const int cen_idx = __ldg(&center[b]);
    const float4* Wv   = reinterpret_cast<const float4*>(W);
    const float4* cenp = Wv + (size_t)cen_idx * (KB_D / 4);
    const float4  cen0 = __ldg(&cenp[lane]);

    float esum = 0.f;

#pragma unroll
    for (int c0 = 0; c0 < KB_C; c0 += BATCH) {
        // 8 independent LDG.128 in flight; indices re-shuffled on demand
        float4 r[BATCH];
#pragma unroll
        for (int k = 0; k < BATCH; k++) {
            const int idx = __shfl_sync(0xffffffffu, my_idx, c0 + k);
            r[k] = __ldg(&Wv[(size_t)idx * (KB_D / 4) + lane]);
        }

        // fixed-point lower bound + single-instruction warp reduction per row
        int s[BATCH];
#pragma unroll
        for (int k = 0; k < BATCH; k++) {
            const float p = fminf(quarter_d2(r[k], cen0), 60000.f);
            s[k] = __reduce_add_sync(0xffffffffu, __float2int_rd(p * 1024.f));
        }

        // warp-uniform survivor dispatch (rare)
#pragma unroll
        for (int k = 0; k < BATCH; k++) {
            if (s[k] <= T_INT) {
                const int idx = __shfl_sync(0xffffffffu, my_idx, c0 + k);
                esum += slow_path(&Wv[(size_t)idx * (KB_D / 4)], cenp, cen0, lane, sacc);
            }
        }
    }

    const float inv = 1.0f / (esum + 1e-8f);
    float4* op = reinterpret_cast<float4*>(out + (size_t)b * KB_D);
#pragma unroll
    for (int i = 0; i < 4; i++) {
        float4 v = sacc[lane + 32 * i];
        v.x *= inv; v.y *= inv; v.z *= inv; v.w *= inv;
        __stcs(&op[lane + 32 * i], v);
    }
}

extern "C" void kernel_launch(void* const* d_in, const int* in_sizes, int n_in,
                              void* d_out, int out_size)
{
    const int* context = (const int*)d_in[0];
    const int* center  = (const int*)d_in[1];
    const float* W     = (const float*)d_in[2];
    for (int i = 0; i < n_in; i++) {
        if (in_sizes[i] == KB_B * KB_C)      context = (const int*)d_in[i];
        else if (in_sizes[i] == KB_B)        center  = (const int*)d_in[i];
        else if (in_sizes[i] > KB_B * KB_C)  W       = (const float*)d_in[i];
    }
    float* out = (float*)d_out;
    const int nblocks = KB_B / WARPS_PER_BLOCK;
    kre_kernel<<<nblocks, NTHREADS>>>(context, center, W, out);
}

// round 7
// speedup vs baseline: 2.6113x; 1.1738x over previous
#include <cuda_runtime.h>

// KREmbedding: Gaussian-weighted context embedding aggregation.
// context: [B, C] int32, center: [B] int32, W: [V, D] float32 -> out [B, D] float32
// B=8192, C=32, D=512, SIGMA=1.0
//
// Round 7: 2 warps per batch row + all-REDUX bound cascade.
//   expf(-d2/2) == 0.0f exactly when d2 > ~208 (fp32 underflow). Partial sums
//   of squares lower-bound d2; each lane converts its partial p to fixed point
//   floor(min(p,60000)*1024) (<= 1024p, *1024 exact), one redux.sync.add.s32
//   gives warp-uniform S <= 1024*d2. S > 220*1024 proves w == 0.0f (identical
//   in the fp32 reference). Stage 1: first 128 elems, 8 rows batched (MLP=8).
//   Stage 2 (surviving ~13%): next 128 elems, REDUX again (no shfl tree).
//   Full exact fp32 path only for true near-collisions (~few per grid).
//   Each warp owns 16 of the 32 context rows; pair combines via smem epilogue.
//   grid=4096 -> 3.1 waves -> small tail (fixes R6's 1.5-wave quantization).

#define KB_B 8192
#define KB_C 32
#define KB_D 512
#define NTHREADS 128            // 4 warps = 2 batch rows per block
#define BATCH 8
#define T_SKIP 220.0f
#define T_INT (220 * 1024)

__device__ __forceinline__ float warp_sum(float v) {
#pragma unroll
    for (int off = 16; off; off >>= 1)
        v += __shfl_xor_sync(0xffffffffu, v, off);
    return v;
}

__device__ __forceinline__ float quarter_d2(float4 r, float4 c) {
    float dx = r.x - c.x, dy = r.y - c.y, dz = r.z - c.z, dw = r.w - c.w;
    float d = dx * dx;
    d = fmaf(dy, dy, d);
    d = fmaf(dz, dz, d);
    d = fmaf(dw, dw, d);
    return d;
}

__device__ __forceinline__ int bound_int(float p) {
    return __float2int_rd(fminf(p, 60000.f) * 1024.f);   // floor -> lower bound
}

// Cold path (warp-uniform entry, ~13% of rows). Stage-2 REDUX bound first;
// the exact fp32 computation runs only for near/exact collisions.
__device__ __noinline__ float slow_path(const float4* __restrict__ rowp,
                                        const float4* __restrict__ cenp,
                                        float4 cen0, int s1, int lane,
                                        float4* __restrict__ sacc)
{
    const float4 r1   = __ldg(&rowp[lane + 32]);
    const float4 cen1 = __ldg(&cenp[lane + 32]);
    const int s2 = s1 + __reduce_add_sync(0xffffffffu, bound_int(quarter_d2(r1, cen1)));
    if (s2 > T_INT) return 0.f;                    // provably w == 0.0f (256-elem bound)

    // exact full path (collisions / near-collisions only)
    const float4 r0   = __ldg(&rowp[lane]);
    const float4 cen2 = __ldg(&cenp[lane + 64]);
    const float4 cen3 = __ldg(&cenp[lane + 96]);
    const float4 r2   = __ldg(&rowp[lane + 64]);
    const float4 r3   = __ldg(&rowp[lane + 96]);
    const float t  = warp_sum(quarter_d2(r0, cen0) + quarter_d2(r1, cen1));
    const float d2 = t + warp_sum(quarter_d2(r2, cen2) + quarter_d2(r3, cen3));

    const float e = __expf(-0.5f * d2);

    float4 a;
    a = sacc[lane];
    a.x = fmaf(e, r0.x, a.x); a.y = fmaf(e, r0.y, a.y);
    a.z = fmaf(e, r0.z, a.z); a.w = fmaf(e, r0.w, a.w);
    sacc[lane] = a;
    a = sacc[lane + 32];
    a.x = fmaf(e, r1.x, a.x); a.y = fmaf(e, r1.y, a.y);
    a.z = fmaf(e, r1.z, a.z); a.w = fmaf(e, r1.w, a.w);
    sacc[lane + 32] = a;
    a = sacc[lane + 64];
    a.x = fmaf(e, r2.x, a.x); a.y = fmaf(e, r2.y, a.y);
    a.z = fmaf(e, r2.z, a.z); a.w = fmaf(e, r2.w, a.w);
    sacc[lane + 64] = a;
    a = sacc[lane + 96];
    a.x = fmaf(e, r3.x, a.x); a.y = fmaf(e, r3.y, a.y);
    a.z = fmaf(e, r3.z, a.z); a.w = fmaf(e, r3.w, a.w);
    sacc[lane + 96] = a;
    return e;
}

__global__ __launch_bounds__(NTHREADS)
void kre_kernel(const int* __restrict__ context,
                const int* __restrict__ center,
                const float* __restrict__ W,
                float* __restrict__ out)
{
    const int tid  = threadIdx.x;
    const int lane = tid & 31;
    const int wid  = tid >> 5;
    const int b    = blockIdx.x * 2 + (wid >> 1);  // 2 warps per batch row
    const int half = wid & 1;                       // which 16 context rows

    __shared__ float4 s_acc[4][KB_D / 4];           // per-warp slices (8 KB)
    __shared__ float  s_esum[4];
    float4* sacc = s_acc[wid];
#pragma unroll
    for (int i = 0; i < 4; i++)
        sacc[lane + 32 * i] = make_float4(0.f, 0.f, 0.f, 0.f);

    // lanes 0-15 / 16-31 hold duplicate copies; shfl from lane (c0+k) is valid
    const int my_idx  = __ldg(&context[b * KB_C + half * 16 + (lane & 15)]);
    const int cen_idx = __ldg(&center[b]);
    const float4* Wv   = reinterpret_cast<const float4*>(W);
    const float4* cenp = Wv + (size_t)cen_idx * (KB_D / 4);
    const float4  cen0 = __ldg(&cenp[lane]);

    float esum = 0.f;

#pragma unroll
    for (int c0 = 0; c0 < 16; c0 += BATCH) {
        float4 r[BATCH];
#pragma unroll
        for (int k = 0; k < BATCH; k++) {
            const int idx = __shfl_sync(0xffffffffu, my_idx, c0 + k);
            r[k] = __ldg(&Wv[(size_t)idx * (KB_D / 4) + lane]);
        }

        int s[BATCH];
#pragma unroll
        for (int k = 0; k < BATCH; k++)
            s[k] = __reduce_add_sync(0xffffffffu, bound_int(quarter_d2(r[k], cen0)));

#pragma unroll
        for (int k = 0; k < BATCH; k++) {
            if (s[k] <= T_INT) {
                const int idx = __shfl_sync(0xffffffffu, my_idx, c0 + k);
                esum += slow_path(&Wv[(size_t)idx * (KB_D / 4)], cenp, cen0,
                                  s[k], lane, sacc);
            }
        }
    }

    if (lane == 0) s_esum[wid] = esum;
    __syncthreads();

    // pair combine: warps {0,1} -> b0, warps {2,3} -> b1; 64 lanes per pair
    const int pair  = tid >> 6;                    // 0 or 1
    const int ptid  = tid & 63;
    const int b_out = blockIdx.x * 2 + pair;
    const float inv = 1.0f / (s_esum[pair * 2] + s_esum[pair * 2 + 1] + 1e-8f);

    float4* op = reinterpret_cast<float4*>(out + (size_t)b_out * KB_D);
#pragma unroll
    for (int i = 0; i < 2; i++) {
        const int j = ptid + 64 * i;
        const float4 a0 = s_acc[pair * 2][j];
        const float4 a1 = s_acc[pair * 2 + 1][j];
        float4 v;
        v.x = (a0.x + a1.x) * inv;
        v.y = (a0.y + a1.y) * inv;
        v.z = (a0.z + a1.z) * inv;
        v.w = (a0.w + a1.w) * inv;
        __stcs(&op[j], v);
    }
}

extern "C" void kernel_launch(void* const* d_in, const int* in_sizes, int n_in,
                              void* d_out, int out_size)
{
    const int* context = (const int*)d_in[0];
    const int* center  = (const int*)d_in[1];
    const float* W     = (const float*)d_in[2];
    for (int i = 0; i < n_in; i++) {
        if (in_sizes[i] == KB_B * KB_C)      context = (const int*)d_in[i];
        else if (in_sizes[i] == KB_B)        center  = (const int*)d_in[i];
        else if (in_sizes[i] > KB_B * KB_C)  W       = (const float*)d_in[i];
    }
    float* out = (float*)d_out;
    kre_kernel<<<KB_B / 2, NTHREADS>>>(context, center, W, out);
}

// round 8
// speedup vs baseline: 3.2505x; 1.2448x over previous
#include <cuda_runtime.h>

// KREmbedding: Gaussian-weighted context embedding aggregation.
// context: [B, C] int32, center: [B] int32, W: [V, D] float32 -> out [B, D] float32
// B=8192, C=32, D=512, SIGMA=1.0
//
// Round 8: 160-element stage-1 bound + min-folded dispatch.
//   expf(-d2/2) == 0.0f exactly when d2 > ~208 (fp32 underflow). Partial sums
//   of squares lower-bound d2. Each lane's partial over its 5 elements
//   (float4 over elems 0-127, +1 scalar over elems 128-159) is converted to
//   fixed point floor(min(p,60000)*1024) (*1024 exact, floor -> lower bound);
//   one redux.sync.add.s32 gives warp-uniform S <= 1024*d2. S > 220*1024
//   proves w == 0.0f in the fp32 reference too. At 160 elems survival ~0.3%,
//   so the slow path is ~never taken; survivor dispatch is guarded by a single
//   min-folded branch per 8-row batch (common case: 1 compare, 0 calls).
//   2 warps per b (16 rows each), pair-combine via smem epilogue, grid=4096.

#define KB_B 8192
#define KB_C 32
#define KB_D 512
#define NTHREADS 128            // 4 warps = 2 batch rows per block
#define BATCH 8
#define T_INT (220 * 1024)

__device__ __forceinline__ float warp_sum(float v) {
#pragma unroll
    for (int off = 16; off; off >>= 1)
        v += __shfl_xor_sync(0xffffffffu, v, off);
    return v;
}

__device__ __forceinline__ float quarter_d2(float4 r, float4 c) {
    float dx = r.x - c.x, dy = r.y - c.y, dz = r.z - c.z, dw = r.w - c.w;
    float d = dx * dx;
    d = fmaf(dy, dy, d);
    d = fmaf(dz, dz, d);
    d = fmaf(dw, dw, d);
    return d;
}

__device__ __forceinline__ int bound_int(float p) {
    return __float2int_rd(fminf(p, 60000.f) * 1024.f);   // floor -> lower bound
}

// Cold path: warp-uniform entry, ~0.3% of rows (near/exact collisions plus a
// thin statistical tail). Recomputes the exact full fp32 distance from L1-hot
// data, then exp + accumulate. A 256-element REDUX bound prunes first.
__device__ __noinline__ float slow_path(const float4* __restrict__ rowp,
                                        const float4* __restrict__ cenp,
                                        float4 cen0, int lane,
                                        float4* __restrict__ sacc)
{
    const float4 r1   = __ldg(&rowp[lane + 32]);
    const float4 cen1 = __ldg(&cenp[lane + 32]);
    // 256-element bound (recompute stage-1 part exactly; still a lower bound)
    const float4 r0 = __ldg(&rowp[lane]);
    const float pa  = quarter_d2(r0, cen0) + quarter_d2(r1, cen1);
    const int s2 = __reduce_add_sync(0xffffffffu, bound_int(pa));
    if (s2 > T_INT) return 0.f;                    // provably w == 0.0f

    const float4 cen2 = __ldg(&cenp[lane + 64]);
    const float4 cen3 = __ldg(&cenp[lane + 96]);
    const float4 r2   = __ldg(&rowp[lane + 64]);
    const float4 r3   = __ldg(&rowp[lane + 96]);
    const float t  = warp_sum(pa);
    const float d2 = t + warp_sum(quarter_d2(r2, cen2) + quarter_d2(r3, cen3));

    const float e = __expf(-0.5f * d2);

    float4 a;
    a = sacc[lane];
    a.x = fmaf(e, r0.x, a.x); a.y = fmaf(e, r0.y, a.y);
    a.z = fmaf(e, r0.z, a.z); a.w = fmaf(e, r0.w, a.w);
    sacc[lane] = a;
    a = sacc[lane + 32];
    a.x = fmaf(e, r1.x, a.x); a.y = fmaf(e, r1.y, a.y);
    a.z = fmaf(e, r1.z, a.z); a.w = fmaf(e, r1.w, a.w);
    sacc[lane + 32] = a;
    a = sacc[lane + 64];
    a.x = fmaf(e, r2.x, a.x); a.y = fmaf(e, r2.y, a.y);
    a.z = fmaf(e, r2.z, a.z); a.w = fmaf(e, r2.w, a.w);
    sacc[lane + 64] = a;
    a = sacc[lane + 96];
    a.x = fmaf(e, r3.x, a.x); a.y = fmaf(e, r3.y, a.y);
    a.z = fmaf(e, r3.z, a.z); a.w = fmaf(e, r3.w, a.w);
    sacc[lane + 96] = a;
    return e;
}

__global__ __launch_bounds__(NTHREADS)
void kre_kernel(const int* __restrict__ context,
                const int* __restrict__ center,
                const float* __restrict__ W,
                float* __restrict__ out)
{
    const int tid  = threadIdx.x;
    const int lane = tid & 31;
    const int wid  = tid >> 5;
    const int b    = blockIdx.x * 2 + (wid >> 1);  // 2 warps per batch row
    const int half = wid & 1;                      // which 16 context rows

    __shared__ float4 s_acc[4][KB_D / 4];          // per-warp slices (8 KB)
    __shared__ float  s_esum[4];
    float4* sacc = s_acc[wid];
#pragma unroll
    for (int i = 0; i < 4; i++)
        sacc[lane + 32 * i] = make_float4(0.f, 0.f, 0.f, 0.f);

    const int my_idx  = __ldg(&context[b * KB_C + half * 16 + (lane & 15)]);
    const int cen_idx = __ldg(&center[b]);
    const float*  Wf   = W;
    const float4* Wv   = reinterpret_cast<const float4*>(W);
    const float4* cenp = Wv + (size_t)cen_idx * (KB_D / 4);
    const float4  cen0 = __ldg(&cenp[lane]);
    const float   cen4 = __ldg(&Wf[(size_t)cen_idx * KB_D + 128 + lane]); // elems 128-159

    float esum = 0.f;

#pragma unroll
    for (int c0 = 0; c0 < 16; c0 += BATCH) {
        int s[BATCH];
#pragma unroll
        for (int k = 0; k < BATCH; k++) {
            const int idx = __shfl_sync(0xffffffffu, my_idx, c0 + k);
            const float4 r  = __ldg(&Wv[(size_t)idx * (KB_D / 4) + lane]);
            const float  r4 = __ldg(&Wf[(size_t)idx * KB_D + 128 + lane]);
            const float  dx = r4 - cen4;
            const float  p  = fmaf(dx, dx, quarter_d2(r, cen0));   // 160-elem partial
            s[k] = __reduce_add_sync(0xffffffffu, bound_int(p));
        }

        // min-fold: one branch per batch in the common (no-survivor) case
        int smin = s[0];
#pragma unroll
        for (int k = 1; k < BATCH; k++) smin = min(smin, s[k]);

        if (smin <= T_INT) {                        // rare (~2% of batches)
#pragma unroll
            for (int k = 0; k < BATCH; k++) {
                if (s[k] <= T_INT) {
                    const int idx = __shfl_sync(0xffffffffu, my_idx, c0 + k);
                    esum += slow_path(&Wv[(size_t)idx * (KB_D / 4)], cenp,
                                      cen0, lane, sacc);
                }
            }
        }
    }

    if (lane == 0) s_esum[wid] = esum;
    __syncthreads();

    // pair combine: warps {0,1} -> b0, warps {2,3} -> b1; 64 lanes per pair
    const int pair  = tid >> 6;
    const int ptid  = tid & 63;
    const int b_out = blockIdx.x * 2 + pair;
    const float inv = 1.0f / (s_esum[pair * 2] + s_esum[pair * 2 + 1] + 1e-8f);

    float4* op = reinterpret_cast<float4*>(out + (size_t)b_out * KB_D);
#pragma unroll
    for (int i = 0; i < 2; i++) {
        const int j = ptid + 64 * i;
        const float4 a0 = s_acc[pair * 2][j];
        const float4 a1 = s_acc[pair * 2 + 1][j];
        float4 v;
        v.x = (a0.x + a1.x) * inv;
        v.y = (a0.y + a1.y) * inv;
        v.z = (a0.z + a1.z) * inv;
        v.w = (a0.w + a1.w) * inv;
        __stcs(&op[j], v);
    }
}

extern "C" void kernel_launch(void* const* d_in, const int* in_sizes, int n_in,
                              void* d_out, int out_size)
{
    const int* context = (const int*)d_in[0];
    const int* center  = (const int*)d_in[1];
    const float* W     = (const float*)d_in[2];
    for (int i = 0; i < n_in; i++) {
        if (in_sizes[i] == KB_B * KB_C)      context = (const int*)d_in[i];
        else if (in_sizes[i] == KB_B)        center  = (const int*)d_in[i];
        else if (in_sizes[i] > KB_B * KB_C)  W       = (const float*)d_in[i];
    }
    float* out = (float*)d_out;
    kre_kernel<<<KB_B / 2, NTHREADS>>>(context, center, W, out);
}

// round 9
// speedup vs baseline: 3.2567x; 1.0019x over previous
#include <cuda_runtime.h>

// KREmbedding: Gaussian-weighted context embedding aggregation.
// context: [B, C] int32, center: [B] int32, W: [V, D] float32 -> out [B, D] float32
// B=8192, C=32, D=512, SIGMA=1.0
//
// Round 9: single 16-row pipelined batch + occupancy 10 blocks/SM.
//   Bound: expf(-d2/2)==0.0f exactly when d2>~208 (fp32 underflow). Partial
//   sums of squares lower-bound d2. Per row, lanes cover 160 elems (float4 on
//   elems 0..127 + scalar on 128..159); fixed point floor(min(p,60000)*1024)
//   (*1024 exact, floor->lower bound), one redux.sync.add.s32 -> warp-uniform
//   S <= 1024*d2; S > 220*1024 proves w==0.0f in the fp32 reference too
//   (survival ~0.3%). All 16 rows in ONE flat loop: loads stay continuously
//   in flight (only s[16] is live), single min-folded survivor branch.
//   __launch_bounds__(128,10) caps regs ~51 -> 40 warps/SM (62.5% occ).

#define KB_B 8192
#define KB_C 32
#define KB_D 512
#define NTHREADS 128            // 4 warps = 2 batch rows per block
#define ROWS_PER_WARP 16
#define T_INT (220 * 1024)
#define ROW_BYTES (KB_D * 4)    // 2048; idx*2048 fits in 32 bits (V=50000)

__device__ __forceinline__ float warp_sum(float v) {
#pragma unroll
    for (int off = 16; off; off >>= 1)
        v += __shfl_xor_sync(0xffffffffu, v, off);
    return v;
}

__device__ __forceinline__ float quarter_d2(float4 r, float4 c) {
    float dx = r.x - c.x, dy = r.y - c.y, dz = r.z - c.z, dw = r.w - c.w;
    float d = dx * dx;
    d = fmaf(dy, dy, d);
    d = fmaf(dz, dz, d);
    d = fmaf(dw, dw, d);
    return d;
}

__device__ __forceinline__ int bound_int(float p) {
    return __float2int_rd(fminf(p, 60000.f) * 1024.f);   // floor -> lower bound
}

// Cold path: warp-uniform entry, ~0.3% of rows. Exact full fp32 distance from
// L1-hot data, then exp + accumulate. 256-element REDUX bound prunes first.
__device__ __noinline__ float slow_path(const float4* __restrict__ rowp,
                                        const float4* __restrict__ cenp,
                                        float4 cen0, int lane,
                                        float4* __restrict__ sacc)
{
    const float4 r1   = __ldg(&rowp[lane + 32]);
    const float4 cen1 = __ldg(&cenp[lane + 32]);
    const float4 r0   = __ldg(&rowp[lane]);
    const float pa  = quarter_d2(r0, cen0) + quarter_d2(r1, cen1);
    const int s2 = __reduce_add_sync(0xffffffffu, bound_int(pa));
    if (s2 > T_INT) return 0.f;                    // provably w == 0.0f

    const float4 cen2 = __ldg(&cenp[lane + 64]);
    const float4 cen3 = __ldg(&cenp[lane + 96]);
    const float4 r2   = __ldg(&rowp[lane + 64]);
    const float4 r3   = __ldg(&rowp[lane + 96]);
    const float t  = warp_sum(pa);
    const float d2 = t + warp_sum(quarter_d2(r2, cen2) + quarter_d2(r3, cen3));

    const float e = __expf(-0.5f * d2);

    float4 a;
    a = sacc[lane];
    a.x = fmaf(e, r0.x, a.x); a.y = fmaf(e, r0.y, a.y);
    a.z = fmaf(e, r0.z, a.z); a.w = fmaf(e, r0.w, a.w);
    sacc[lane] = a;
    a = sacc[lane + 32];
    a.x = fmaf(e, r1.x, a.x); a.y = fmaf(e, r1.y, a.y);
    a.z = fmaf(e, r1.z, a.z); a.w = fmaf(e, r1.w, a.w);
    sacc[lane + 32] = a;
    a = sacc[lane + 64];
    a.x = fmaf(e, r2.x, a.x); a.y = fmaf(e, r2.y, a.y);
    a.z = fmaf(e, r2.z, a.z); a.w = fmaf(e, r2.w, a.w);
    sacc[lane + 64] = a;
    a = sacc[lane + 96];
    a.x = fmaf(e, r3.x, a.x); a.y = fmaf(e, r3.y, a.y);
    a.z = fmaf(e, r3.z, a.z); a.w = fmaf(e, r3.w, a.w);
    sacc[lane + 96] = a;
    return e;
}

__global__ __launch_bounds__(NTHREADS, 10)
void kre_kernel(const int* __restrict__ context,
                const int* __restrict__ center,
                const float* __restrict__ W,
                float* __restrict__ out)
{
    const int tid  = threadIdx.x;
    const int lane = tid & 31;
    const int wid  = tid >> 5;
    const int b    = blockIdx.x * 2 + (wid >> 1);  // 2 warps per batch row
    const int half = wid & 1;                      // which 16 context rows

    __shared__ float4 s_acc[4][KB_D / 4];          // per-warp slices (8 KB)
    __shared__ float  s_esum[4];
    float4* sacc = s_acc[wid];
#pragma unroll
    for (int i = 0; i < 4; i++)
        sacc[lane + 32 * i] = make_float4(0.f, 0.f, 0.f, 0.f);

    const int my_idx  = __ldg(&context[b * KB_C + half * 16 + (lane & 15)]);
    const int cen_idx = __ldg(&center[b]);
    const char* Wb = reinterpret_cast<const char*>(W);
    const char* cenb = Wb + (unsigned)cen_idx * ROW_BYTES;
    const float4* cenp = reinterpret_cast<const float4*>(cenb);
    const float4  cen0 = __ldg(&cenp[lane]);
    const float   cen4 = __ldg(reinterpret_cast<const float*>(cenb) + 128 + lane);

    float esum = 0.f;

    // ---- single flat 16-row pipelined bound pass ----
    int s[ROWS_PER_WARP];
#pragma unroll
    for (int k = 0; k < ROWS_PER_WARP; k++) {
        const int idx = __shfl_sync(0xffffffffu, my_idx, k);
        const char* rowb = Wb + (unsigned)idx * ROW_BYTES;
        const float4 r  = __ldg(reinterpret_cast<const float4*>(rowb) + lane);
        const float  r4 = __ldg(reinterpret_cast<const float*>(rowb) + 128 + lane);
        const float  dx = r4 - cen4;
        const float  p  = fmaf(dx, dx, quarter_d2(r, cen0));    // 160-elem partial
        s[k] = __reduce_add_sync(0xffffffffu, bound_int(p));
    }

    // min-fold: one branch for all 16 rows in the common case
    int smin = s[0];
#pragma unroll
    for (int k = 1; k < ROWS_PER_WARP; k++) smin = min(smin, s[k]);

    if (smin <= T_INT) {                            // rare (~4% of warps)
#pragma unroll
        for (int k = 0; k < ROWS_PER_WARP; k++) {
            if (s[k] <= T_INT) {
                const int idx = __shfl_sync(0xffffffffu, my_idx, k);
                const float4* rowp =
                    reinterpret_cast<const float4*>(Wb + (unsigned)idx * ROW_BYTES);
                esum += slow_path(rowp, cenp, cen0, lane, sacc);
            }
        }
    }

    if (lane == 0) s_esum[wid] = esum;
    __syncthreads();

    // pair combine: warps {0,1} -> b0, warps {2,3} -> b1; 64 lanes per pair
    const int pair  = tid >> 6;
    const int ptid  = tid & 63;
    const int b_out = blockIdx.x * 2 + pair;
    const float inv = 1.0f / (s_esum[pair * 2] + s_esum[pair * 2 + 1] + 1e-8f);

    float4* op = reinterpret_cast<float4*>(out + (size_t)b_out * KB_D);
#pragma unroll
    for (int i = 0; i < 2; i++) {
        const int j = ptid + 64 * i;
        const float4 a0 = s_acc[pair * 2][j];
        const float4 a1 = s_acc[pair * 2 + 1][j];
        float4 v;
        v.x = (a0.x + a1.x) * inv;
        v.y = (a0.y + a1.y) * inv;
        v.z = (a0.z + a1.z) * inv;
        v.w = (a0.w + a1.w) * inv;
        __stcs(&op[j], v);
    }
}

extern "C" void kernel_launch(void* const* d_in, const int* in_sizes, int n_in,
                              void* d_out, int out_size)
{
    const int* context = (const int*)d_in[0];
    const int* center  = (const int*)d_in[1];
    const float* W     = (const float*)d_in[2];
    for (int i = 0; i < n_in; i++) {
        if (in_sizes[i] == KB_B * KB_C)      context = (const int*)d_in[i];
        else if (in_sizes[i] == KB_B)        center  = (const int*)d_in[i];
        else if (in_sizes[i] > KB_B * KB_C)  W       = (const float*)d_in[i];
    }
    float* out = (float*)d_out;
    kre_kernel<<<KB_B / 2, NTHREADS>>>(context, center, W, out);
}